// round 1
// baseline (speedup 1.0000x reference)
#include <cuda_runtime.h>
#include <math.h>

// Problem constants
#define TOK  2048     // B*S tokens
#define HDIM 2048
#define FDIM 7168
#define NEXP 8
#define TOPK 2

// GEMM tiling
#define BM 128
#define BN 128
#define BK 8

// ---------------- scratch (static device globals; no allocation) ----------------
__device__ int   g_cnt[NEXP];                     // tokens routed per expert
__device__ int   g_tok[NEXP * TOK];               // slot -> token id
__device__ int   g_dst[NEXP * TOK];               // slot -> row in g_partial (= t*TOPK + k)
__device__ float g_wt [NEXP * TOK];               // slot -> combine weight
__device__ float g_hid[(size_t)NEXP * TOK * FDIM];        // 470 MB: SwiGLU hidden per expert-slot
__device__ float g_partial[(size_t)TOK * TOPK * HDIM];    // 33.5 MB: per-(token,k) expert output

// ---------------- kernels ----------------

__global__ void zero_kernel() {
    if (threadIdx.x < NEXP) g_cnt[threadIdx.x] = 0;
}

// One block per token: fp32 gate logits, top-2 (jax tie-break: lower index wins),
// softmax over the two selected logits, atomic slot assignment.
__global__ void route_kernel(const float* __restrict__ x, const float* __restrict__ gw) {
    const int t   = blockIdx.x;
    const int tid = threadIdx.x;   // 256 threads

    float acc[NEXP];
#pragma unroll
    for (int e = 0; e < NEXP; e++) acc[e] = 0.f;

    const float* xt = x + (size_t)t * HDIM;
    for (int h = tid; h < HDIM; h += 256) {
        float xv = xt[h];
#pragma unroll
        for (int e = 0; e < NEXP; e++) acc[e] += xv * gw[h * NEXP + e];
    }

    __shared__ float s[NEXP][256];
#pragma unroll
    for (int e = 0; e < NEXP; e++) s[e][tid] = acc[e];
    __syncthreads();

    for (int off = 128; off > 0; off >>= 1) {
        if (tid < off) {
#pragma unroll
            for (int e = 0; e < NEXP; e++) s[e][tid] += s[e][tid + off];
        }
        __syncthreads();
    }

    if (tid == 0) {
        float v[NEXP];
#pragma unroll
        for (int e = 0; e < NEXP; e++) v[e] = s[e][0];

        int i1 = 0;
#pragma unroll
        for (int e = 1; e < NEXP; e++) if (v[e] > v[i1]) i1 = e;   // strict >: lowest idx on tie
        int i2 = (i1 == 0) ? 1 : 0;
#pragma unroll
        for (int e = 0; e < NEXP; e++)
            if (e != i1 && v[e] > v[i2]) i2 = e;

        float m  = fmaxf(v[i1], v[i2]);
        float e1 = __expf(v[i1] - m);
        float e2 = __expf(v[i2] - m);
        float inv = 1.f / (e1 + e2);

        int s0 = atomicAdd(&g_cnt[i1], 1);
        g_tok[i1 * TOK + s0] = t;
        g_dst[i1 * TOK + s0] = t * TOPK + 0;
        g_wt [i1 * TOK + s0] = e1 * inv;

        int s1 = atomicAdd(&g_cnt[i2], 1);
        g_tok[i2 * TOK + s1] = t;
        g_dst[i2 * TOK + s1] = t * TOPK + 1;
        g_wt [i2 * TOK + s1] = e2 * inv;
    }
}

// Grouped GEMM 1 (fused): for expert e, rows = gathered tokens,
//   h1 = X@w1_e, h3 = X@w3_e, hid = silu(h1)*h3
__global__ __launch_bounds__(256, 1)
void gemm1_kernel(const float* __restrict__ x,
                  const float* __restrict__ w1,
                  const float* __restrict__ w3) {
    const int e   = blockIdx.z;
    const int n_e = g_cnt[e];
    const int m0  = blockIdx.y * BM;
    if (m0 >= n_e) return;
    const int n0  = blockIdx.x * BN;

    const float* W1   = w1 + (size_t)e * HDIM * FDIM;
    const float* W3   = w3 + (size_t)e * HDIM * FDIM;
    const int*   toks = g_tok + e * TOK;

    __shared__ float As [BK][BM];
    __shared__ float B1s[BK][BN];
    __shared__ float B3s[BK][BN];

    const int tid = threadIdx.x;

    // A loader: 2 threads per row, float4 each
    const int arow  = tid >> 1;
    const int apart = (tid & 1) * 4;
    const int grow  = m0 + arow;
    const bool avalid = (grow < n_e);
    const float* aptr = avalid ? (x + (size_t)toks[grow] * HDIM + apart) : nullptr;

    // B loader: 8 k-rows x 32 float4 columns
    const int bk = tid >> 5;
    const int bn = (tid & 31) * 4;

    const int tx = tid & 15;
    const int ty = tid >> 4;

    float acc1[8][8], acc3[8][8];
#pragma unroll
    for (int i = 0; i < 8; i++)
#pragma unroll
        for (int j = 0; j < 8; j++) { acc1[i][j] = 0.f; acc3[i][j] = 0.f; }

    for (int k0 = 0; k0 < HDIM; k0 += BK) {
        float4 av = avalid ? *(const float4*)(aptr + k0) : make_float4(0.f, 0.f, 0.f, 0.f);
        As[apart + 0][arow] = av.x;
        As[apart + 1][arow] = av.y;
        As[apart + 2][arow] = av.z;
        As[apart + 3][arow] = av.w;

        *(float4*)&B1s[bk][bn] = *(const float4*)(W1 + (size_t)(k0 + bk) * FDIM + n0 + bn);
        *(float4*)&B3s[bk][bn] = *(const float4*)(W3 + (size_t)(k0 + bk) * FDIM + n0 + bn);
        __syncthreads();

#pragma unroll
        for (int kk = 0; kk < BK; kk++) {
            float a[8], b1r[8], b3r[8];
#pragma unroll
            for (int i = 0; i < 8; i++) a[i] = As[kk][ty * 8 + i];
#pragma unroll
            for (int j = 0; j < 8; j++) { b1r[j] = B1s[kk][tx * 8 + j]; b3r[j] = B3s[kk][tx * 8 + j]; }
#pragma unroll
            for (int i = 0; i < 8; i++)
#pragma unroll
                for (int j = 0; j < 8; j++) {
                    acc1[i][j] += a[i] * b1r[j];
                    acc3[i][j] += a[i] * b3r[j];
                }
        }
        __syncthreads();
    }

    // epilogue: silu(h1)*h3 -> g_hid
#pragma unroll
    for (int i = 0; i < 8; i++) {
        int row = m0 + ty * 8 + i;
        if (row >= n_e) continue;
        float* dst = g_hid + ((size_t)e * TOK + row) * FDIM + n0 + tx * 8;
#pragma unroll
        for (int j = 0; j < 8; j++) {
            float h1 = acc1[i][j];
            float h3 = acc3[i][j];
            dst[j] = (h1 / (1.f + __expf(-h1))) * h3;
        }
    }
}

// Grouped GEMM 2: eo = hid @ w2_e, scaled by combine weight, scattered to g_partial
__global__ __launch_bounds__(256, 1)
void gemm2_kernel(const float* __restrict__ w2) {
    const int e   = blockIdx.z;
    const int n_e = g_cnt[e];
    const int m0  = blockIdx.y * BM;
    if (m0 >= n_e) return;
    const int n0  = blockIdx.x * BN;

    const float* A = g_hid + (size_t)e * TOK * FDIM;
    const float* W = w2 + (size_t)e * FDIM * HDIM;

    __shared__ float As[BK][BM];
    __shared__ float Bs[BK][BN];

    const int tid = threadIdx.x;

    const int arow  = tid >> 1;
    const int apart = (tid & 1) * 4;
    const int grow  = m0 + arow;
    const bool avalid = (grow < n_e);
    const float* aptr = A + (size_t)grow * FDIM + apart;

    const int bk = tid >> 5;
    const int bn = (tid & 31) * 4;

    const int tx = tid & 15;
    const int ty = tid >> 4;

    float acc[8][8];
#pragma unroll
    for (int i = 0; i < 8; i++)
#pragma unroll
        for (int j = 0; j < 8; j++) acc[i][j] = 0.f;

    for (int k0 = 0; k0 < FDIM; k0 += BK) {
        float4 av = avalid ? *(const float4*)(aptr + k0) : make_float4(0.f, 0.f, 0.f, 0.f);
        As[apart + 0][arow] = av.x;
        As[apart + 1][arow] = av.y;
        As[apart + 2][arow] = av.z;
        As[apart + 3][arow] = av.w;

        *(float4*)&Bs[bk][bn] = *(const float4*)(W + (size_t)(k0 + bk) * HDIM + n0 + bn);
        __syncthreads();

#pragma unroll
        for (int kk = 0; kk < BK; kk++) {
            float a[8], br[8];
#pragma unroll
            for (int i = 0; i < 8; i++) a[i] = As[kk][ty * 8 + i];
#pragma unroll
            for (int j = 0; j < 8; j++) br[j] = Bs[kk][tx * 8 + j];
#pragma unroll
            for (int i = 0; i < 8; i++)
#pragma unroll
                for (int j = 0; j < 8; j++) acc[i][j] += a[i] * br[j];
        }
        __syncthreads();
    }

#pragma unroll
    for (int i = 0; i < 8; i++) {
        int row = m0 + ty * 8 + i;
        if (row >= n_e) continue;
        int   drow = g_dst[e * TOK + row];
        float w    = g_wt [e * TOK + row];
        float* dst = g_partial + (size_t)drow * HDIM + n0 + tx * 8;
#pragma unroll
        for (int j = 0; j < 8; j++) dst[j] = w * acc[i][j];
    }
}

// out[t][h] = partial[t][0][h] + partial[t][1][h]   (float4 vectorized)
__global__ void combine_kernel(float* __restrict__ out) {
    const size_t i = (size_t)blockIdx.x * 256 + threadIdx.x;   // float4 index over TOK*HDIM/4
    const int c = HDIM / 4;
    const size_t t = i / c;
    const size_t j = i % c;
    const float4* p = (const float4*)g_partial;
    float4 a = p[(t * 2 + 0) * c + j];
    float4 b = p[(t * 2 + 1) * c + j];
    float4 r;
    r.x = a.x + b.x; r.y = a.y + b.y; r.z = a.z + b.z; r.w = a.w + b.w;
    ((float4*)out)[i] = r;
}

// ---------------- launch ----------------
extern "C" void kernel_launch(void* const* d_in, const int* in_sizes, int n_in,
                              void* d_out, int out_size) {
    const float* x  = (const float*)d_in[0];
    const float* gw = (const float*)d_in[1];
    const float* w1 = (const float*)d_in[2];
    const float* w3 = (const float*)d_in[3];
    const float* w2 = (const float*)d_in[4];
    float* out = (float*)d_out;

    zero_kernel<<<1, 32>>>();
    route_kernel<<<TOK, 256>>>(x, gw);

    dim3 g1(FDIM / BN, TOK / BM, NEXP);
    gemm1_kernel<<<g1, 256>>>(x, w1, w3);

    dim3 g2(HDIM / BN, TOK / BM, NEXP);
    gemm2_kernel<<<g2, 256>>>(w2);

    combine_kernel<<<(TOK * HDIM / 4) / 256, 256>>>(out);
}

// round 7
// speedup vs baseline: 1.8853x; 1.8853x over previous
#include <cuda_runtime.h>
#include <mma.h>
#include <math.h>
#include <stdint.h>

using namespace nvcuda;

#define TOK  2048
#define HDIM 2048
#define FDIM 7168
#define NEXP 8
#define TOPK 2

#define BM 128
#define BN 128
#define BK 32
#define NC1 (HDIM / BK)   // 64
#define NC2 (FDIM / BK)   // 224

#define ALD 40            // A smem row stride (floats), 160B rows
#define BLD 136           // B smem row stride (floats), 544B rows
#define CLD 136

#define ASZ (BM * ALD)        // 5120 floats
#define BSZ (BK * BLD)        // 4352 floats
#define STG1 (ASZ + 2 * BSZ)  // 13824 floats / 55296 B
#define STG2 (ASZ + BSZ)      //  9472 floats / 37888 B
#define DYN1 (2 * STG1 * 4)   // 110592 B
#define DYN2 (2 * STG2 * 4)   //  75776 B

// ---------------- scratch ----------------
__device__ int   g_cnt[NEXP];
__device__ int   g_tok[NEXP * TOK];
__device__ int   g_dst[NEXP * TOK];
__device__ float g_wt [NEXP * TOK];
__device__ float g_hid[(size_t)NEXP * TOK * FDIM];       // 470 MB
__device__ float g_partial[(size_t)TOK * TOPK * HDIM];   // 33.5 MB

// ---------------- helpers ----------------
__device__ __forceinline__ float tff(float f) {
    // round-to-nearest tf32 (zero-mean error; HW mma would truncate)
    uint32_t r; asm("cvt.rna.tf32.f32 %0, %1;" : "=r"(r) : "f"(f));
    return __uint_as_float(r);
}

// ---------------- small kernels ----------------
__global__ void zero_kernel() {
    if (threadIdx.x < NEXP) g_cnt[threadIdx.x] = 0;
}

// fp32 gate: exact top-2 matches jax.lax.top_k (strict > keeps lowest index on ties)
__global__ void route_kernel(const float* __restrict__ x, const float* __restrict__ gw) {
    const int t   = blockIdx.x;
    const int tid = threadIdx.x;

    float acc[NEXP];
#pragma unroll
    for (int e = 0; e < NEXP; e++) acc[e] = 0.f;

    const float* xt = x + (size_t)t * HDIM;
    for (int h = tid; h < HDIM; h += 256) {
        float xv = xt[h];
#pragma unroll
        for (int e = 0; e < NEXP; e++) acc[e] += xv * gw[h * NEXP + e];
    }

    __shared__ float s[NEXP][256];
#pragma unroll
    for (int e = 0; e < NEXP; e++) s[e][tid] = acc[e];
    __syncthreads();
    for (int off = 128; off > 0; off >>= 1) {
        if (tid < off) {
#pragma unroll
            for (int e = 0; e < NEXP; e++) s[e][tid] += s[e][tid + off];
        }
        __syncthreads();
    }

    if (tid == 0) {
        float v[NEXP];
#pragma unroll
        for (int e = 0; e < NEXP; e++) v[e] = s[e][0];
        int i1 = 0;
#pragma unroll
        for (int e = 1; e < NEXP; e++) if (v[e] > v[i1]) i1 = e;
        int i2 = (i1 == 0) ? 1 : 0;
#pragma unroll
        for (int e = 0; e < NEXP; e++)
            if (e != i1 && v[e] > v[i2]) i2 = e;

        float m  = fmaxf(v[i1], v[i2]);
        float e1 = __expf(v[i1] - m);
        float e2 = __expf(v[i2] - m);
        float inv = 1.f / (e1 + e2);

        int s0 = atomicAdd(&g_cnt[i1], 1);
        g_tok[i1 * TOK + s0] = t;
        g_dst[i1 * TOK + s0] = t * TOPK + 0;
        g_wt [i1 * TOK + s0] = e1 * inv;
        int s1 = atomicAdd(&g_cnt[i2], 1);
        g_tok[i2 * TOK + s1] = t;
        g_dst[i2 * TOK + s1] = t * TOPK + 1;
        g_wt [i2 * TOK + s1] = e2 * inv;
    }
}

// ---------------- GEMM1: hid = silu(X@W1) * (X@W3), grouped by expert ----------------
__global__ __launch_bounds__(256)
void gemm1_kernel(const float* __restrict__ x,
                  const float* __restrict__ w1,
                  const float* __restrict__ w3) {
    extern __shared__ float sm[];
    const int ex  = blockIdx.z;
    const int n_e = g_cnt[ex];
    const int m0  = blockIdx.x * BM;
    if (m0 >= n_e) return;
    const int n0  = blockIdx.y * BN;
    const int tid = threadIdx.x;
    const int wid = tid >> 5;

    // loader geometry
    const int rbase = tid >> 3, c4 = tid & 7;   // A: rows rbase+32it, float4 col c4
    const int kb    = tid >> 5, nb = tid & 31;  // B: k-rows kb+8it, float4 col nb

    const float* aptr[4];
#pragma unroll
    for (int it = 0; it < 4; it++) {
        int rc = m0 + rbase + 32 * it;
        if (rc > n_e - 1) rc = n_e - 1;
        aptr[it] = x + (size_t)g_tok[ex * TOK + rc] * HDIM + c4 * 4;
    }
    const float* b1p = w1 + (size_t)ex * HDIM * FDIM + (size_t)kb * FDIM + n0 + nb * 4;
    const float* b3p = w3 + (size_t)ex * HDIM * FDIM + (size_t)kb * FDIM + n0 + nb * 4;

    wmma::fragment<wmma::accumulator, 16, 16, 8, float> acc1[4][2], acc3[4][2];
#pragma unroll
    for (int i = 0; i < 4; i++)
#pragma unroll
        for (int j = 0; j < 2; j++) {
            wmma::fill_fragment(acc1[i][j], 0.f);
            wmma::fill_fragment(acc3[i][j], 0.f);
        }

    const int wm = wid & 1, wn = wid >> 1;   // warp tile: rows wm*64, cols wn*32

    float4 ra[4], rb1[4], rb3[4];

    auto ldg_all = [&](int c) {
        const int k0 = c * BK;
#pragma unroll
        for (int it = 0; it < 4; it++) ra[it] = *(const float4*)(aptr[it] + k0);
#pragma unroll
        for (int it = 0; it < 4; it++) {
            rb1[it] = *(const float4*)(b1p + (size_t)(k0 + 8 * it) * FDIM);
            rb3[it] = *(const float4*)(b3p + (size_t)(k0 + 8 * it) * FDIM);
        }
    };
    auto sts_all = [&](int buf) {
        float* As  = sm + buf * STG1;
        float* B1s = As + ASZ;
        float* B3s = As + ASZ + BSZ;
#pragma unroll
        for (int it = 0; it < 4; it++) {
            float* d = As + (rbase + 32 * it) * ALD + c4 * 4;
            d[0] = tff(ra[it].x); d[1] = tff(ra[it].y);
            d[2] = tff(ra[it].z); d[3] = tff(ra[it].w);
        }
#pragma unroll
        for (int it = 0; it < 4; it++) {
            float* d1 = B1s + (kb + 8 * it) * BLD + nb * 4;
            d1[0] = tff(rb1[it].x); d1[1] = tff(rb1[it].y);
            d1[2] = tff(rb1[it].z); d1[3] = tff(rb1[it].w);
            float* d3 = B3s + (kb + 8 * it) * BLD + nb * 4;
            d3[0] = tff(rb3[it].x); d3[1] = tff(rb3[it].y);
            d3[2] = tff(rb3[it].z); d3[3] = tff(rb3[it].w);
        }
    };

    ldg_all(0);
    for (int c = 0; c < NC1; c++) {
        sts_all(c & 1);
        __syncthreads();
        if (c + 1 < NC1) ldg_all(c + 1);

        const float* As  = sm + (c & 1) * STG1;
        const float* B1s = As + ASZ;
        const float* B3s = As + ASZ + BSZ;
#pragma unroll
        for (int kc = 0; kc < BK; kc += 8) {
            wmma::fragment<wmma::matrix_a, 16, 16, 8, wmma::precision::tf32, wmma::row_major> af[4];
            wmma::fragment<wmma::matrix_b, 16, 16, 8, wmma::precision::tf32, wmma::row_major> bf1[2], bf3[2];
#pragma unroll
            for (int i = 0; i < 4; i++)
                wmma::load_matrix_sync(af[i], As + (wm * 64 + i * 16) * ALD + kc, ALD);
#pragma unroll
            for (int j = 0; j < 2; j++) {
                wmma::load_matrix_sync(bf1[j], B1s + kc * BLD + wn * 32 + j * 16, BLD);
                wmma::load_matrix_sync(bf3[j], B3s + kc * BLD + wn * 32 + j * 16, BLD);
            }
#pragma unroll
            for (int i = 0; i < 4; i++)
#pragma unroll
                for (int j = 0; j < 2; j++) {
                    wmma::mma_sync(acc1[i][j], af[i], bf1[j], acc1[i][j]);
                    wmma::mma_sync(acc3[i][j], af[i], bf3[j], acc3[i][j]);
                }
        }
        __syncthreads();
    }

    // epilogue: silu(h1)*h3 elementwise on fragments (identical mapping), direct global store
    float* hidb = g_hid + (size_t)ex * TOK * FDIM;
#pragma unroll
    for (int i = 0; i < 4; i++) {
        int row = m0 + wm * 64 + i * 16;
#pragma unroll
        for (int j = 0; j < 2; j++) {
#pragma unroll
            for (int t = 0; t < acc1[i][j].num_elements; t++) {
                float h1 = acc1[i][j].x[t];
                float h3 = acc3[i][j].x[t];
                float h  = (h1 / (1.f + __expf(-h1))) * h3;
                acc1[i][j].x[t] = tff(h);   // pre-round so gemm2 skips cvt on A
            }
            wmma::store_matrix_sync(hidb + (size_t)row * FDIM + n0 + wn * 32 + j * 16,
                                    acc1[i][j], FDIM, wmma::mem_row_major);
        }
    }
}

// ---------------- GEMM2: partial = (hid @ W2) * combine_wt, row-scattered ----------------
__global__ __launch_bounds__(256)
void gemm2_kernel(const float* __restrict__ w2) {
    extern __shared__ float sm[];
    const int ex  = blockIdx.z;
    const int n_e = g_cnt[ex];
    const int m0  = blockIdx.x * BM;
    if (m0 >= n_e) return;
    const int n0  = blockIdx.y * BN;
    const int tid = threadIdx.x;
    const int wid = tid >> 5;

    const int rbase = tid >> 3, c4 = tid & 7;
    const int kb    = tid >> 5, nb = tid & 31;

    const float* aptr = g_hid + ((size_t)ex * TOK + m0 + rbase) * FDIM + c4 * 4;
    const float* bp   = w2 + (size_t)ex * FDIM * HDIM + (size_t)kb * HDIM + n0 + nb * 4;

    wmma::fragment<wmma::accumulator, 16, 16, 8, float> acc[4][2];
#pragma unroll
    for (int i = 0; i < 4; i++)
#pragma unroll
        for (int j = 0; j < 2; j++) wmma::fill_fragment(acc[i][j], 0.f);

    const int wm = wid & 1, wn = wid >> 1;

    float4 ra[4], rb[4];
    auto ldg_all = [&](int c) {
        const int k0 = c * BK;
#pragma unroll
        for (int it = 0; it < 4; it++)
            ra[it] = *(const float4*)(aptr + (size_t)it * 32 * FDIM + k0);
#pragma unroll
        for (int it = 0; it < 4; it++)
            rb[it] = *(const float4*)(bp + (size_t)(k0 + 8 * it) * HDIM);
    };
    auto sts_all = [&](int buf) {
        float* As = sm + buf * STG2;
        float* Bs = As + ASZ;
#pragma unroll
        for (int it = 0; it < 4; it++) {
            float* d = As + (rbase + 32 * it) * ALD + c4 * 4;
            d[0] = ra[it].x; d[1] = ra[it].y; d[2] = ra[it].z; d[3] = ra[it].w;  // already tf32
        }
#pragma unroll
        for (int it = 0; it < 4; it++) {
            float* d = Bs + (kb + 8 * it) * BLD + nb * 4;
            d[0] = tff(rb[it].x); d[1] = tff(rb[it].y);
            d[2] = tff(rb[it].z); d[3] = tff(rb[it].w);
        }
    };

    ldg_all(0);
    for (int c = 0; c < NC2; c++) {
        sts_all(c & 1);
        __syncthreads();
        if (c + 1 < NC2) ldg_all(c + 1);

        const float* As = sm + (c & 1) * STG2;
        const float* Bs = As + ASZ;
#pragma unroll
        for (int kc = 0; kc < BK; kc += 8) {
            wmma::fragment<wmma::matrix_a, 16, 16, 8, wmma::precision::tf32, wmma::row_major> af[4];
            wmma::fragment<wmma::matrix_b, 16, 16, 8, wmma::precision::tf32, wmma::row_major> bf[2];
#pragma unroll
            for (int i = 0; i < 4; i++)
                wmma::load_matrix_sync(af[i], As + (wm * 64 + i * 16) * ALD + kc, ALD);
#pragma unroll
            for (int j = 0; j < 2; j++)
                wmma::load_matrix_sync(bf[j], Bs + kc * BLD + wn * 32 + j * 16, BLD);
#pragma unroll
            for (int i = 0; i < 4; i++)
#pragma unroll
                for (int j = 0; j < 2; j++)
                    wmma::mma_sync(acc[i][j], af[i], bf[j], acc[i][j]);
        }
        __syncthreads();
    }

    // epilogue: stage to smem, scale by combine weight, scatter rows
    float* Cs = sm;
#pragma unroll
    for (int i = 0; i < 4; i++)
#pragma unroll
        for (int j = 0; j < 2; j++)
            wmma::store_matrix_sync(Cs + (wm * 64 + i * 16) * CLD + wn * 32 + j * 16,
                                    acc[i][j], CLD, wmma::mem_row_major);
    __syncthreads();

#pragma unroll
    for (int it = 0; it < 16; it++) {
        int idx = tid + 256 * it;          // float4 index: 128 rows x 32
        int r = idx >> 5, cc = idx & 31;
        if (m0 + r < n_e) {
            int   drow = g_dst[ex * TOK + m0 + r];
            float w    = g_wt [ex * TOK + m0 + r];
            const float* src = Cs + r * CLD + cc * 4;
            float4 v;
            v.x = w * src[0]; v.y = w * src[1]; v.z = w * src[2]; v.w = w * src[3];
            *(float4*)(g_partial + (size_t)drow * HDIM + n0 + cc * 4) = v;
        }
    }
}

__global__ void combine_kernel(float* __restrict__ out) {
    const size_t i = (size_t)blockIdx.x * 256 + threadIdx.x;
    const int c = HDIM / 4;
    const size_t t = i / c;
    const size_t j = i % c;
    const float4* p = (const float4*)g_partial;
    float4 a = p[(t * 2 + 0) * c + j];
    float4 b = p[(t * 2 + 1) * c + j];
    float4 r;
    r.x = a.x + b.x; r.y = a.y + b.y; r.z = a.z + b.z; r.w = a.w + b.w;
    ((float4*)out)[i] = r;
}

// ---------------- launch ----------------
extern "C" void kernel_launch(void* const* d_in, const int* in_sizes, int n_in,
                              void* d_out, int out_size) {
    const float* x  = (const float*)d_in[0];
    const float* gw = (const float*)d_in[1];
    const float* w1 = (const float*)d_in[2];
    const float* w3 = (const float*)d_in[3];
    const float* w2 = (const float*)d_in[4];
    float* out = (float*)d_out;

    cudaFuncSetAttribute(gemm1_kernel, cudaFuncAttributeMaxDynamicSharedMemorySize, DYN1);
    cudaFuncSetAttribute(gemm2_kernel, cudaFuncAttributeMaxDynamicSharedMemorySize, DYN2);

    zero_kernel<<<1, 32>>>();
    route_kernel<<<TOK, 256>>>(x, gw);

    dim3 g1(TOK / BM, FDIM / BN, NEXP);
    gemm1_kernel<<<g1, 256, DYN1>>>(x, w1, w3);

    dim3 g2(TOK / BM, HDIM / BN, NEXP);
    gemm2_kernel<<<g2, 256, DYN2>>>(w2);

    combine_kernel<<<(TOK * HDIM / 4) / 256, 256>>>(out);
}

// round 8
// speedup vs baseline: 5.7902x; 3.0713x over previous
#include <cuda_runtime.h>
#include <cuda_fp16.h>
#include <mma.h>
#include <math.h>
#include <stdint.h>

using namespace nvcuda;

#define TOK  2048
#define HDIM 2048
#define FDIM 7168
#define NEXP 8
#define TOPK 2

#define BM 128
#define BN 128
#define BK 32
#define NC1 (HDIM / BK)   // 64
#define NC2 (FDIM / BK)   // 224

#define ALDH 40           // A smem row stride (halves): 32 data + 8 pad = 80B (16B-mult)
#define BLDH 136          // B smem row stride (halves): 128 data + 8 pad = 272B
#define CLD  136          // epilogue float stride

#define ASZH (BM * ALDH)          // 5120 halves
#define BSZH (BK * BLDH)          // 4352 halves
#define STG1H (ASZH + 2 * BSZH)   // 13824 halves = 27648 B
#define STG2H (ASZH + BSZH)       //  9472 halves = 18944 B
#define DYN1 (3 * STG1H * 2)      // 82944 B (3-stage)
#define DYN2 (4 * STG2H * 2)      // 75776 B (4-stage)

// ---------------- scratch ----------------
__device__ int    g_cnt[NEXP];
__device__ int    g_tok[NEXP * TOK];
__device__ int    g_dst[NEXP * TOK];
__device__ float  g_wt [NEXP * TOK];
__device__ __half g_xh  [(size_t)TOK * HDIM];                //   8 MB
__device__ __half g_w1h [(size_t)NEXP * HDIM * FDIM];        // 235 MB
__device__ __half g_w3h [(size_t)NEXP * HDIM * FDIM];        // 235 MB
__device__ __half g_w2h [(size_t)NEXP * FDIM * HDIM];        // 235 MB
__device__ __half g_hidh[(size_t)NEXP * TOK * FDIM];         // 235 MB
__device__ float  g_partial[(size_t)TOK * TOPK * HDIM];      //  33 MB

// ---------------- helpers ----------------
__device__ __forceinline__ uint32_t smem_u32(const void* p) {
    uint32_t a;
    asm("{ .reg .u64 t; cvta.to.shared.u64 t, %1; cvt.u32.u64 %0, t; }" : "=r"(a) : "l"(p));
    return a;
}
__device__ __forceinline__ void cpa(uint32_t s, const void* g) {
    asm volatile("cp.async.cg.shared.global [%0], [%1], 16;" :: "r"(s), "l"(g));
}
__device__ __forceinline__ void cpcommit() { asm volatile("cp.async.commit_group;"); }
template <int N>
__device__ __forceinline__ void cpwait() { asm volatile("cp.async.wait_group %0;" :: "n"(N)); }

// ---------------- small kernels ----------------
__global__ void zero_kernel() {
    if (threadIdx.x < NEXP) g_cnt[threadIdx.x] = 0;
}

// fp32 gate: exact top-2 matches jax.lax.top_k (strict > keeps lowest index on ties)
__global__ void route_kernel(const float* __restrict__ x, const float* __restrict__ gw) {
    const int t   = blockIdx.x;
    const int tid = threadIdx.x;

    float acc[NEXP];
#pragma unroll
    for (int e = 0; e < NEXP; e++) acc[e] = 0.f;

    const float* xt = x + (size_t)t * HDIM;
    for (int h = tid; h < HDIM; h += 256) {
        float xv = xt[h];
#pragma unroll
        for (int e = 0; e < NEXP; e++) acc[e] += xv * gw[h * NEXP + e];
    }

    __shared__ float s[NEXP][256];
#pragma unroll
    for (int e = 0; e < NEXP; e++) s[e][tid] = acc[e];
    __syncthreads();
    for (int off = 128; off > 0; off >>= 1) {
        if (tid < off) {
#pragma unroll
            for (int e = 0; e < NEXP; e++) s[e][tid] += s[e][tid + off];
        }
        __syncthreads();
    }

    if (tid == 0) {
        float v[NEXP];
#pragma unroll
        for (int e = 0; e < NEXP; e++) v[e] = s[e][0];
        int i1 = 0;
#pragma unroll
        for (int e = 1; e < NEXP; e++) if (v[e] > v[i1]) i1 = e;
        int i2 = (i1 == 0) ? 1 : 0;
#pragma unroll
        for (int e = 0; e < NEXP; e++)
            if (e != i1 && v[e] > v[i2]) i2 = e;

        float m  = fmaxf(v[i1], v[i2]);
        float e1 = __expf(v[i1] - m);
        float e2 = __expf(v[i2] - m);
        float inv = 1.f / (e1 + e2);

        int s0 = atomicAdd(&g_cnt[i1], 1);
        g_tok[i1 * TOK + s0] = t;
        g_dst[i1 * TOK + s0] = t * TOPK + 0;
        g_wt [i1 * TOK + s0] = e1 * inv;
        int s1 = atomicAdd(&g_cnt[i2], 1);
        g_tok[i2 * TOK + s1] = t;
        g_dst[i2 * TOK + s1] = t * TOPK + 1;
        g_wt [i2 * TOK + s1] = e2 * inv;
    }
}

// fp32 -> fp16 (RN), 8 elems/thread; grid covers n/8 exactly
__global__ void f2h_kernel(const float* __restrict__ s, __half* __restrict__ d) {
    const size_t i = ((size_t)blockIdx.x * 256 + threadIdx.x) * 8;
    float4 a = *(const float4*)(s + i);
    float4 b = *(const float4*)(s + i + 4);
    __half2 h0 = __floats2half2_rn(a.x, a.y);
    __half2 h1 = __floats2half2_rn(a.z, a.w);
    __half2 h2 = __floats2half2_rn(b.x, b.y);
    __half2 h3 = __floats2half2_rn(b.z, b.w);
    uint4 o;
    o.x = *(uint32_t*)&h0; o.y = *(uint32_t*)&h1;
    o.z = *(uint32_t*)&h2; o.w = *(uint32_t*)&h3;
    *(uint4*)(d + i) = o;
}

// ---------------- GEMM1: hid = silu(X@W1) * (X@W3) ----------------
__global__ __launch_bounds__(256)
void gemm1_kernel() {
    extern __shared__ __half sm[];
    const int ex  = blockIdx.z;
    const int n_e = g_cnt[ex];
    const int m0  = blockIdx.x * BM;
    if (m0 >= n_e) return;
    const int n0  = blockIdx.y * BN;
    const int tid = threadIdx.x;
    const int wid = tid >> 5;
    const int wm  = wid & 1, wn = wid >> 1;

    const uint32_t smb = smem_u32(sm);

    // A loader: 2 chunks (16B) per thread; row r = tid>>1
    const int ar = tid >> 1, acb = (tid & 1) * 2;
    int rc = m0 + ar; if (rc > n_e - 1) rc = n_e - 1;
    const __half* asrc = g_xh + (size_t)g_tok[ex * TOK + rc] * HDIM + acb * 8;
    const uint32_t aoff = (ar * ALDH + acb * 8) * 2;

    // B loaders: 2 chunks each for B1/B3; k-row rb = tid>>3
    const int rb = tid >> 3, bcb = (tid & 7) * 2;
    const __half* b1src = g_w1h + (size_t)ex * HDIM * FDIM + (size_t)rb * FDIM + n0 + bcb * 8;
    const __half* b3src = g_w3h + (size_t)ex * HDIM * FDIM + (size_t)rb * FDIM + n0 + bcb * 8;
    const uint32_t boff = (rb * BLDH + bcb * 8) * 2;

    auto issue = [&](int c) {
        const uint32_t base = smb + (uint32_t)(c % 3) * (STG1H * 2);
        const int k0 = c * BK;
        cpa(base + aoff,      asrc + k0);
        cpa(base + aoff + 16, asrc + k0 + 8);
        const __half* s1 = b1src + (size_t)k0 * FDIM;
        const __half* s3 = b3src + (size_t)k0 * FDIM;
        const uint32_t b1b = base + ASZH * 2 + boff;
        const uint32_t b3b = base + (ASZH + BSZH) * 2 + boff;
        cpa(b1b, s1); cpa(b1b + 16, s1 + 8);
        cpa(b3b, s3); cpa(b3b + 16, s3 + 8);
        cpcommit();
    };

    wmma::fragment<wmma::accumulator, 16, 16, 16, float> acc1[4][2], acc3[4][2];
#pragma unroll
    for (int i = 0; i < 4; i++)
#pragma unroll
        for (int j = 0; j < 2; j++) {
            wmma::fill_fragment(acc1[i][j], 0.f);
            wmma::fill_fragment(acc3[i][j], 0.f);
        }

    issue(0); issue(1);
    for (int c = 0; c < NC1; c++) {
        if (c + 2 < NC1) { issue(c + 2); cpwait<2>(); }
        else if (c + 1 < NC1) cpwait<1>();
        else cpwait<0>();
        __syncthreads();

        const __half* As  = sm + (c % 3) * STG1H;
        const __half* B1s = As + ASZH;
        const __half* B3s = As + ASZH + BSZH;
#pragma unroll
        for (int kc = 0; kc < BK; kc += 16) {
            wmma::fragment<wmma::matrix_a, 16, 16, 16, __half, wmma::row_major> af[4];
            wmma::fragment<wmma::matrix_b, 16, 16, 16, __half, wmma::row_major> bf1[2], bf3[2];
#pragma unroll
            for (int i = 0; i < 4; i++)
                wmma::load_matrix_sync(af[i], As + (wm * 64 + i * 16) * ALDH + kc, ALDH);
#pragma unroll
            for (int j = 0; j < 2; j++) {
                wmma::load_matrix_sync(bf1[j], B1s + kc * BLDH + wn * 32 + j * 16, BLDH);
                wmma::load_matrix_sync(bf3[j], B3s + kc * BLDH + wn * 32 + j * 16, BLDH);
            }
#pragma unroll
            for (int i = 0; i < 4; i++)
#pragma unroll
                for (int j = 0; j < 2; j++) {
                    wmma::mma_sync(acc1[i][j], af[i], bf1[j], acc1[i][j]);
                    wmma::mma_sync(acc3[i][j], af[i], bf3[j], acc3[i][j]);
                }
        }
        __syncthreads();
    }

    // epilogue: silu(h1)*h3, two 64-row phases through smem, fp16 global store
    float* Cs = (float*)sm;   // 64 x CLD floats = 34816 B
    __half* hidb = g_hidh + (size_t)ex * TOK * FDIM;
#pragma unroll 1
    for (int p = 0; p < 2; p++) {
        if (wm == p) {
#pragma unroll
            for (int i = 0; i < 4; i++)
#pragma unroll
                for (int j = 0; j < 2; j++) {
#pragma unroll
                    for (int t = 0; t < acc1[i][j].num_elements; t++) {
                        float h1 = acc1[i][j].x[t];
                        float h3 = acc3[i][j].x[t];
                        acc1[i][j].x[t] = (h1 / (1.f + __expf(-h1))) * h3;
                    }
                    wmma::store_matrix_sync(Cs + (i * 16) * CLD + wn * 32 + j * 16,
                                            acc1[i][j], CLD, wmma::mem_row_major);
                }
        }
        __syncthreads();
#pragma unroll
        for (int it = 0; it < 4; it++) {
            int u = tid + 256 * it;                 // 1024 chunks: 64 rows x 16
            int r = u >> 4, c8 = u & 15;
            int grow = m0 + p * 64 + r;
            if (grow < n_e) {
                const float* src = Cs + r * CLD + c8 * 8;
                __half2 h0 = __floats2half2_rn(src[0], src[1]);
                __half2 h1 = __floats2half2_rn(src[2], src[3]);
                __half2 h2 = __floats2half2_rn(src[4], src[5]);
                __half2 h3 = __floats2half2_rn(src[6], src[7]);
                uint4 o;
                o.x = *(uint32_t*)&h0; o.y = *(uint32_t*)&h1;
                o.z = *(uint32_t*)&h2; o.w = *(uint32_t*)&h3;
                *(uint4*)(hidb + (size_t)grow * FDIM + n0 + c8 * 8) = o;
            }
        }
        __syncthreads();
    }
}

// ---------------- GEMM2: partial = (hid @ W2) * combine_wt, row-scattered ----------------
__global__ __launch_bounds__(256)
void gemm2_kernel() {
    extern __shared__ __half sm[];
    const int ex  = blockIdx.z;
    const int n_e = g_cnt[ex];
    const int m0  = blockIdx.x * BM;
    if (m0 >= n_e) return;
    const int n0  = blockIdx.y * BN;
    const int tid = threadIdx.x;
    const int wid = tid >> 5;
    const int wm  = wid & 1, wn = wid >> 1;

    const uint32_t smb = smem_u32(sm);

    const int ar = tid >> 1, acb = (tid & 1) * 2;
    const __half* asrc = g_hidh + ((size_t)ex * TOK + m0 + ar) * FDIM + acb * 8;
    const uint32_t aoff = (ar * ALDH + acb * 8) * 2;

    const int rb = tid >> 3, bcb = (tid & 7) * 2;
    const __half* bsrc = g_w2h + (size_t)ex * FDIM * HDIM + (size_t)rb * HDIM + n0 + bcb * 8;
    const uint32_t boff = (rb * BLDH + bcb * 8) * 2;

    auto issue = [&](int c) {
        const uint32_t base = smb + (uint32_t)(c & 3) * (STG2H * 2);
        const int k0 = c * BK;
        cpa(base + aoff,      asrc + k0);
        cpa(base + aoff + 16, asrc + k0 + 8);
        const __half* s2 = bsrc + (size_t)k0 * HDIM;
        const uint32_t bb = base + ASZH * 2 + boff;
        cpa(bb, s2); cpa(bb + 16, s2 + 8);
        cpcommit();
    };

    wmma::fragment<wmma::accumulator, 16, 16, 16, float> acc[4][2];
#pragma unroll
    for (int i = 0; i < 4; i++)
#pragma unroll
        for (int j = 0; j < 2; j++) wmma::fill_fragment(acc[i][j], 0.f);

    issue(0); issue(1); issue(2);
    for (int c = 0; c < NC2; c++) {
        if (c + 3 < NC2) { issue(c + 3); cpwait<3>(); }
        else if (c + 2 < NC2) cpwait<2>();
        else if (c + 1 < NC2) cpwait<1>();
        else cpwait<0>();
        __syncthreads();

        const __half* As = sm + (c & 3) * STG2H;
        const __half* Bs = As + ASZH;
#pragma unroll
        for (int kc = 0; kc < BK; kc += 16) {
            wmma::fragment<wmma::matrix_a, 16, 16, 16, __half, wmma::row_major> af[4];
            wmma::fragment<wmma::matrix_b, 16, 16, 16, __half, wmma::row_major> bf[2];
#pragma unroll
            for (int i = 0; i < 4; i++)
                wmma::load_matrix_sync(af[i], As + (wm * 64 + i * 16) * ALDH + kc, ALDH);
#pragma unroll
            for (int j = 0; j < 2; j++)
                wmma::load_matrix_sync(bf[j], Bs + kc * BLDH + wn * 32 + j * 16, BLDH);
#pragma unroll
            for (int i = 0; i < 4; i++)
#pragma unroll
                for (int j = 0; j < 2; j++)
                    wmma::mma_sync(acc[i][j], af[i], bf[j], acc[i][j]);
        }
        __syncthreads();
    }

    // epilogue: two 64-row phases; scale by combine weight, row-scatter to g_partial
    float* Cs = (float*)sm;
#pragma unroll 1
    for (int p = 0; p < 2; p++) {
        if (wm == p) {
#pragma unroll
            for (int i = 0; i < 4; i++)
#pragma unroll
                for (int j = 0; j < 2; j++)
                    wmma::store_matrix_sync(Cs + (i * 16) * CLD + wn * 32 + j * 16,
                                            acc[i][j], CLD, wmma::mem_row_major);
        }
        __syncthreads();
#pragma unroll
        for (int it = 0; it < 8; it++) {
            int u = tid + 256 * it;                 // 2048 float4: 64 rows x 32
            int r = u >> 5, c4 = u & 31;
            int grow = m0 + p * 64 + r;
            if (grow < n_e) {
                int   drow = g_dst[ex * TOK + grow];
                float w    = g_wt [ex * TOK + grow];
                const float* src = Cs + r * CLD + c4 * 4;
                float4 v;
                v.x = w * src[0]; v.y = w * src[1];
                v.z = w * src[2]; v.w = w * src[3];
                *(float4*)(g_partial + (size_t)drow * HDIM + n0 + c4 * 4) = v;
            }
        }
        __syncthreads();
    }
}

__global__ void combine_kernel(float* __restrict__ out) {
    const size_t i = (size_t)blockIdx.x * 256 + threadIdx.x;
    const int c = HDIM / 4;
    const size_t t = i / c;
    const size_t j = i % c;
    const float4* p = (const float4*)g_partial;
    float4 a = p[(t * 2 + 0) * c + j];
    float4 b = p[(t * 2 + 1) * c + j];
    float4 r;
    r.x = a.x + b.x; r.y = a.y + b.y; r.z = a.z + b.z; r.w = a.w + b.w;
    ((float4*)out)[i] = r;
}

// ---------------- launch ----------------
extern "C" void kernel_launch(void* const* d_in, const int* in_sizes, int n_in,
                              void* d_out, int out_size) {
    const float* x  = (const float*)d_in[0];
    const float* gw = (const float*)d_in[1];
    const float* w1 = (const float*)d_in[2];
    const float* w3 = (const float*)d_in[3];
    const float* w2 = (const float*)d_in[4];
    float* out = (float*)d_out;

    cudaFuncSetAttribute(gemm1_kernel, cudaFuncAttributeMaxDynamicSharedMemorySize, DYN1);
    cudaFuncSetAttribute(gemm2_kernel, cudaFuncAttributeMaxDynamicSharedMemorySize, DYN2);

    __half* xh;  cudaGetSymbolAddress((void**)&xh,  g_xh);
    __half* w1h; cudaGetSymbolAddress((void**)&w1h, g_w1h);
    __half* w3h; cudaGetSymbolAddress((void**)&w3h, g_w3h);
    __half* w2h; cudaGetSymbolAddress((void**)&w2h, g_w2h);

    zero_kernel<<<1, 32>>>();
    route_kernel<<<TOK, 256>>>(x, gw);

    const size_t wn8 = (size_t)NEXP * HDIM * FDIM / 8;
    f2h_kernel<<<(unsigned)((size_t)TOK * HDIM / 8 / 256), 256>>>(x, xh);
    f2h_kernel<<<(unsigned)(wn8 / 256), 256>>>(w1, w1h);
    f2h_kernel<<<(unsigned)(wn8 / 256), 256>>>(w3, w3h);
    f2h_kernel<<<(unsigned)(wn8 / 256), 256>>>(w2, w2h);

    dim3 g1(TOK / BM, FDIM / BN, NEXP);
    gemm1_kernel<<<g1, 256, DYN1>>>();

    dim3 g2(TOK / BM, HDIM / BN, NEXP);
    gemm2_kernel<<<g2, 256, DYN2>>>();

    combine_kernel<<<(TOK * HDIM / 4) / 256, 256>>>(out);
}